// round 17
// baseline (speedup 1.0000x reference)
#include <cuda_runtime.h>
#include <cuda_fp16.h>
#include <math.h>
#include <stdint.h>

// ---------------- problem constants ----------------
#define BB 256
#define TT 128
#define FF 784
#define FFP 832              // FF padded to multiple of 64
#define HH 1024
#define CC 10
#define M1 (BB*TT)
#define BN_EPS 1e-3f

// ---------------- scratch (device globals) ----------------
__device__ __half g_xh  [(size_t)M1 * FFP];        // fp16 x, K-padded
__device__ __half g_wfe [(size_t)FFP * HH];        // fp16 W_fe, K-padded
__device__ __half g_feat[(size_t)M1 * HH];         // fp16 feat, T-MAJOR rows
__device__ __half g_zx  [(size_t)M1 * 4 * HH];     // fp16 Zx (+bias), T-MAJOR, cols j*4+g
__device__ __half g_hseq[(size_t)M1 * HH];         // fp16 h (T,B,H)
__device__ __half g_wg  [(size_t)HH * 4 * HH];     // fp16 kernel, cols PERMUTED j*4+g
__device__ __half g_wrp [(size_t)HH * 4 * HH];     // fp16 rec_kernel, cols PERMUTED j*4+g
__device__ float  g_biasP[4 * HH];                 // bias permuted j*4+g
__device__ volatile unsigned g_bar;

// ---------------- helpers ----------------
__device__ __forceinline__ void cp16(void* dst, const void* src) {
    uint32_t d = (uint32_t)__cvta_generic_to_shared(dst);
    asm volatile("cp.async.cg.shared.global [%0], [%1], 16;" :: "r"(d), "l"(src));
}
#define CP_COMMIT asm volatile("cp.async.commit_group;")
#define CP_WAITN(n) asm volatile("cp.async.wait_group %0;" :: "n"(n))

__device__ __forceinline__ void mma_f16(float* d, const uint32_t* a, const uint32_t* b) {
    asm volatile(
        "mma.sync.aligned.m16n8k16.row.col.f32.f16.f16.f32 "
        "{%0,%1,%2,%3}, {%4,%5,%6,%7}, {%8,%9}, {%0,%1,%2,%3};"
        : "+f"(d[0]), "+f"(d[1]), "+f"(d[2]), "+f"(d[3])
        : "r"(a[0]), "r"(a[1]), "r"(a[2]), "r"(a[3]),
          "r"(b[0]), "r"(b[1]));
}
__device__ __forceinline__ void ldsm_x4(uint32_t& r0, uint32_t& r1, uint32_t& r2,
                                        uint32_t& r3, uint32_t addr) {
    asm volatile("ldmatrix.sync.aligned.m8n8.x4.shared.b16 {%0,%1,%2,%3}, [%4];"
        : "=r"(r0), "=r"(r1), "=r"(r2), "=r"(r3) : "r"(addr));
}
__device__ __forceinline__ void ldsm_x4t(uint32_t& r0, uint32_t& r1, uint32_t& r2,
                                         uint32_t& r3, uint32_t addr) {
    asm volatile("ldmatrix.sync.aligned.m8n8.x4.trans.shared.b16 {%0,%1,%2,%3}, [%4];"
        : "=r"(r0), "=r"(r1), "=r"(r2), "=r"(r3) : "r"(addr));
}

// ---- fast transcendentals: 2 MUFU each ----
#define LOG2E 1.4426950408889634f
__device__ __forceinline__ float ex2f(float x) {
    float y; asm("ex2.approx.f32 %0, %1;" : "=f"(y) : "f"(x)); return y;
}
__device__ __forceinline__ float rcpf(float x) {
    float y; asm("rcp.approx.f32 %0, %1;" : "=f"(y) : "f"(x)); return y;
}
__device__ __forceinline__ float fsig(float x) { return rcpf(1.0f + ex2f(-x * LOG2E)); }
__device__ __forceinline__ float ftanh(float x) { return fmaf(2.0f, fsig(2.0f * x), -1.0f); }

// ---------------- prep kernels ----------------
__global__ void init_kernel() {
    if (threadIdx.x == 0 && blockIdx.x == 0) g_bar = 0u;
}
__global__ void f32_to_f16_kernel(const float2* __restrict__ in,
                                  __half2* __restrict__ out, int n2) {
    int i = blockIdx.x * blockDim.x + threadIdx.x;
    if (i < n2) { float2 v = in[i]; out[i] = __floats2half2_rn(v.x, v.y); }
}
__global__ void pad_f16_kernel(const float* __restrict__ in,
                               __half* __restrict__ out, int rows, int ksrc) {
    int idx = blockIdx.x * blockDim.x + threadIdx.x;
    if (idx < rows * FFP) {
        int r = idx / FFP, c = idx % FFP;
        out[idx] = (c < ksrc) ? __float2half(in[(size_t)r * ksrc + c]) : __half(0.0f);
    }
}
// column permute: Wp[k, j*4+g] = W[k, g*HH+j]
__global__ void permute_w_kernel(const float* __restrict__ W, __half* __restrict__ Wp) {
    int idx = blockIdx.x * blockDim.x + threadIdx.x;
    if (idx < HH * 4 * HH) {
        int k = idx >> 12, c = idx & 4095;
        int j = c >> 2, g = c & 3;
        Wp[idx] = __float2half(W[(size_t)k * 4096 + g * HH + j]);
    }
}
__global__ void permute_bias_kernel(const float* __restrict__ bias, float* __restrict__ bP) {
    int idx = blockIdx.x * blockDim.x + threadIdx.x;
    if (idx < 4 * HH) {
        int j = idx >> 2, g = idx & 3;
        bP[idx] = bias[g * HH + j];
    }
}

// ---------------- fp16 GEMM (time-parallel) ----------------------------------
// EPI 1: feat epilogue -> __half C, T-MAJOR row permute.
// EPI 2: +biasP -> __half C (fp32 accum + fp32 bias, rounded at store).
template<int EPI>
__global__ void __launch_bounds__(512)
gemm_f16(const __half* __restrict__ A, const __half* __restrict__ B,
         __half* __restrict__ C, int M, int N, int K,
         const float* __restrict__ p0, const float* __restrict__ p1,
         const float* __restrict__ p2, const float* __restrict__ p3,
         const float* __restrict__ p4)
{
    constexpr int BM = 256, BN = 128, BK = 64, WM = 64, WN = 32;
    constexpr int MI = WM/16, NI = WN/8, KS = BK/16;
    constexpr int ASTH = BK + 8, BSTH = BN + 8;
    constexpr int ASZH = BM*ASTH, BSZH = BK*BSTH;
    constexpr int AQ8 = BM*BK/8, BQ8 = BK*BN/8;

    extern __shared__ __half smh[];
    __half* As = smh;
    __half* Bs = smh + 2*ASZH;
    const uint32_t As_u = (uint32_t)__cvta_generic_to_shared(As);
    const uint32_t Bs_u = (uint32_t)__cvta_generic_to_shared(Bs);

    const int tid = threadIdx.x, lane = tid & 31, warp = tid >> 5;
    const int wm = (warp / (BN/WN)) * WM, wn = (warp % (BN/WN)) * WN;
    const int row0 = blockIdx.y * BM, col0 = blockIdx.x * BN;

    float acc[MI][NI][4];
#pragma unroll
    for (int mi = 0; mi < MI; mi++)
#pragma unroll
        for (int ni = 0; ni < NI; ni++)
#pragma unroll
            for (int r = 0; r < 4; r++) acc[mi][ni][r] = 0.0f;

    const int KT = K / BK;
#pragma unroll
    for (int q = tid; q < AQ8; q += 512) {
        int r = q >> 3, c = (q & 7) * 8;
        cp16(&As[r*ASTH + c], A + (size_t)(row0 + r)*K + c);
    }
#pragma unroll
    for (int q = tid; q < BQ8; q += 512) {
        int r = q >> 4, c = (q & 15) * 8;
        cp16(&Bs[r*BSTH + c], B + (size_t)r*N + col0 + c);
    }
    CP_COMMIT;

    const int a_m = (lane & 7) + ((lane >> 3) & 1) * 8;
    const int a_k = (lane >> 4) * 8;
    const int b_k = lane & 15;
    const int b_c = (lane >> 4) * 8;

#pragma unroll 1
    for (int kt = 0; kt < KT; kt++) {
        const int cur = kt & 1;
        if (kt + 1 < KT) {
            const int k0 = (kt + 1)*BK, nxt = cur ^ 1;
#pragma unroll
            for (int q = tid; q < AQ8; q += 512) {
                int r = q >> 3, c = (q & 7) * 8;
                cp16(&As[nxt*ASZH + r*ASTH + c], A + (size_t)(row0 + r)*K + k0 + c);
            }
#pragma unroll
            for (int q = tid; q < BQ8; q += 512) {
                int r = q >> 4, c = (q & 15) * 8;
                cp16(&Bs[nxt*BSZH + r*BSTH + c], B + (size_t)(k0 + r)*N + col0 + c);
            }
            CP_COMMIT;
            CP_WAITN(1);
        } else {
            CP_WAITN(0);
        }
        __syncthreads();

#pragma unroll
        for (int ks = 0; ks < KS; ks++) {
            uint32_t afr[MI][4], bfr[NI][2];
#pragma unroll
            for (int mi = 0; mi < MI; mi++) {
                uint32_t addr = As_u + (uint32_t)((cur*ASZH + (wm + mi*16 + a_m)*ASTH
                                                   + ks*16 + a_k) * 2);
                ldsm_x4(afr[mi][0], afr[mi][1], afr[mi][2], afr[mi][3], addr);
            }
#pragma unroll
            for (int n2 = 0; n2 < NI/2; n2++) {
                uint32_t addr = Bs_u + (uint32_t)((cur*BSZH + (ks*16 + b_k)*BSTH
                                                   + wn + n2*16 + b_c) * 2);
                ldsm_x4t(bfr[2*n2][0], bfr[2*n2][1], bfr[2*n2+1][0], bfr[2*n2+1][1], addr);
            }
#pragma unroll
            for (int mi = 0; mi < MI; mi++)
#pragma unroll
                for (int ni = 0; ni < NI; ni++)
                    mma_f16(acc[mi][ni], afr[mi], bfr[ni]);
        }
        __syncthreads();
    }

#pragma unroll
    for (int mi = 0; mi < MI; mi++)
#pragma unroll
        for (int ni = 0; ni < NI; ni++) {
            const int r0 = row0 + wm + mi*16 + (lane >> 2);
            const int c0 = col0 + wn + ni*8 + 2*(lane & 3);
#pragma unroll
            for (int half = 0; half < 2; half++) {
                const int rr = r0 + half*8;
#pragma unroll
                for (int e = 0; e < 2; e++) {
                    const int nn = c0 + e;
                    float v = acc[mi][ni][half*2 + e];
                    if (EPI == 1) {
                        v = ftanh(v + p0[nn]);
                        v = (v - p3[nn]) * rsqrtf(p4[nn] + BN_EPS) * p1[nn] + p2[nn];
                        v = ftanh(v);
                        const int crow = ((rr & (TT - 1)) << 8) + (rr >> 7);
                        C[(size_t)crow*N + nn] = __float2half(v);
                    } else {
                        C[(size_t)rr*N + nn] = __float2half(v + p0[nn]);
                    }
                }
            }
        }
}

// ---------------- persistent fp16 LSTM recurrence -----------------------------
// 128 CTAs x 512 threads; B slab (gate-interleaved cols) smem-resident;
// 3-stage A ring; fp16 Zx with contiguous per-thread gate loads.
#define FBM 128
#define FBK 64
#define FCOLS 64             // 16 j x 4 gates, interleaved j*4+g
#define FASTH (FBK + 8)      // 72
#define FBSTH (FCOLS + 8)    // 72
#define FEPST (FCOLS + 4)    // 68 floats
#define AS_SZH (FBM * FASTH)          // 9216 halves/stage
#define B_SZH  (HH * FBSTH)           // 73728 halves (147456 B)
#define EP_SZ  (FBM * FEPST)          // aliases A stages
#define C_SZ   (FBM * 16)
#define PSMEM_BYTES (3*AS_SZH*2 + B_SZH*2 + C_SZ*4)   // 210944

__global__ void __launch_bounds__(512)
lstm_persistent(const __half* __restrict__ WrP,    // (HH, 4HH) cols j*4+g
                const __half* __restrict__ Zx,     // fp16, t-major, cols j*4+g
                __half* __restrict__ hseq,         // (TT, BB, HH) fp16
                const float* __restrict__ pi, const float* __restrict__ pf,
                const float* __restrict__ po)
{
    extern __shared__ __half dsh[];
    __half* As   = dsh;                        // [3][AS_SZH]
    __half* Bres = dsh + 3*AS_SZH;             // [B_SZH] persistent
    float*  csm  = (float*)(dsh + 3*AS_SZH + B_SZH);
    float*  ep   = (float*)dsh;                // aliases A stages
    const uint32_t As_u = (uint32_t)__cvta_generic_to_shared(As);
    const uint32_t Bs_u = (uint32_t)__cvta_generic_to_shared(Bres);

    const int tid = threadIdx.x, lane = tid & 31, warp = tid >> 5;
    const int wm = (warp >> 1) * 16;
    const int wn = (warp & 1) * 32;
    const int row0 = (blockIdx.x & 1) * FBM;
    const int j0   = (blockIdx.x >> 1) * 16;

    const int j = tid & 15, jg = j0 + j;
    const int mrow = tid >> 4;
    const float pij = pi[jg], pfj = pf[jg], poj = po[jg];

    for (int i = tid; i < C_SZ; i += 512) csm[i] = 0.0f;
    {
        // B slab: rows k of WrP, contiguous 64 cols starting at j0*4
        constexpr int BQ8 = HH * FCOLS / 8;    // 8192
#pragma unroll
        for (int q = tid; q < BQ8; q += 512) {
            int k = q >> 3, c8 = q & 7;
            cp16(&Bres[k*FBSTH + c8*8],
                 WrP + (size_t)k*(4*HH) + j0*4 + c8*8);
        }
        CP_COMMIT;
        CP_WAITN(0);
    }
    __syncthreads();

    constexpr int AQ8 = FBM * FBK / 8;
    constexpr int KT  = HH / FBK;        // 16

    auto load_A = [&](int st, int kt, const __half* hprev) {
#pragma unroll
        for (int q = tid; q < AQ8; q += 512) {
            int r = q >> 3, c = (q & 7) * 8;
            cp16(&As[st*AS_SZH + r*FASTH + c],
                 hprev + (size_t)(row0 + r)*HH + kt*FBK + c);
        }
    };

    const int a_m = (lane & 7) + ((lane >> 3) & 1) * 8;
    const int a_k = (lane >> 4) * 8;
    const int b_k = lane & 15;
    const int b_c = (lane >> 4) * 8;

    // gate inputs for current step: 4 contiguous fp16 per (s) -> float
    float zxr[4][4];
#pragma unroll
    for (int s = 0; s < 4; s++) {
        const int b = row0 + s*32 + mrow;
        const __half2* zp = (const __half2*)(Zx + (size_t)b*(4*HH) + jg*4);
        __half2 z01 = zp[0], z23 = zp[1];
        zxr[s][0] = __low2float(z01);  zxr[s][1] = __high2float(z01);
        zxr[s][2] = __low2float(z23);  zxr[s][3] = __high2float(z23);
    }

#pragma unroll 1
    for (int t = 0; t < TT; t++) {
        float acc[4][4];
#pragma unroll
        for (int ni = 0; ni < 4; ni++)
#pragma unroll
            for (int r = 0; r < 4; r++) acc[ni][r] = 0.0f;

        if (t > 0) {
            const __half* hprev = hseq + (size_t)(t - 1)*BB*HH;
            load_A(0, 0, hprev);
            CP_COMMIT;
            load_A(1, 1, hprev);
            CP_COMMIT;

#pragma unroll 1
            for (int kt = 0; kt < KT; kt++) {
                const int cur = kt % 3;
                if (kt + 1 < KT) { CP_WAITN(1); } else { CP_WAITN(0); }
                __syncthreads();

                if (kt + 2 < KT) {
                    load_A((kt + 2) % 3, kt + 2, hprev);
                    CP_COMMIT;
                }

#pragma unroll
                for (int ks = 0; ks < FBK/16; ks++) {
                    uint32_t afr[4], bfr[4][2];
                    {
                        uint32_t addr = As_u + (uint32_t)((cur*AS_SZH
                                          + (wm + a_m)*FASTH + ks*16 + a_k) * 2);
                        ldsm_x4(afr[0], afr[1], afr[2], afr[3], addr);
                    }
                    const int krow = kt*FBK + ks*16 + b_k;
#pragma unroll
                    for (int n2 = 0; n2 < 2; n2++) {
                        uint32_t addr = Bs_u + (uint32_t)((krow*FBSTH
                                          + wn + n2*16 + b_c) * 2);
                        ldsm_x4t(bfr[2*n2][0], bfr[2*n2][1],
                                 bfr[2*n2+1][0], bfr[2*n2+1][1], addr);
                    }
#pragma unroll
                    for (int ni = 0; ni < 4; ni++)
                        mma_f16(acc[ni], afr, bfr[ni]);
                }
            }
        }
        __syncthreads();   // all MMA smem reads done; ep (alias of As) safe

        // ---- dump accumulators to ep ----
#pragma unroll
        for (int ni = 0; ni < 4; ni++) {
            const int r0 = wm + (lane >> 2);
            const int c0 = wn + ni*8 + 2*(lane & 3);
#pragma unroll
            for (int half = 0; half < 2; half++) {
                ep[(r0 + half*8)*FEPST + c0]     = acc[ni][half*2];
                ep[(r0 + half*8)*FEPST + c0 + 1] = acc[ni][half*2 + 1];
            }
        }
        __syncthreads();

        // ---- gates: float4 zh per (m, j), contiguous ----
        __half* hout = hseq + (size_t)t*BB*HH;
#pragma unroll
        for (int s = 0; s < 4; s++) {
            const int m = s*32 + mrow;
            const int b = row0 + m;

            float4 zh = *(const float4*)&ep[m*FEPST + j*4];
            float zi = zh.x + zxr[s][0];
            float zf = zh.y + zxr[s][1];
            float zc = zh.z + zxr[s][2];
            float zo = zh.w + zxr[s][3];

            float cc = csm[m*16 + j];
            float ig = fsig(zi + cc*pij);
            float fg = fsig(zf + cc*pfj);
            float cn = fg*cc + ig*ftanh(zc);
            float og = fsig(zo + cn*poj);
            float hn = og*ftanh(cn);

            csm[m*16 + j] = cn;
            hout[(size_t)b*HH + jg] = __float2half(hn);
        }

        // ---- step boundary: release barrier + Zx prefetch ----
        if (t + 1 < TT) {
            __syncthreads();
            if (tid == 0)
                asm volatile("red.release.gpu.global.add.u32 [%0], %1;"
                             :: "l"((unsigned*)&g_bar), "r"(1u) : "memory");
#pragma unroll
            for (int s = 0; s < 4; s++) {
                const int b = row0 + s*32 + mrow;
                const __half2* zp = (const __half2*)(Zx
                    + ((size_t)(t + 1)*BB + b)*(4*HH) + jg*4);
                __half2 z01 = zp[0], z23 = zp[1];
                zxr[s][0] = __low2float(z01);  zxr[s][1] = __high2float(z01);
                zxr[s][2] = __low2float(z23);  zxr[s][3] = __high2float(z23);
            }
            if (tid == 0) {
                const unsigned target = 128u * (unsigned)(t + 1);
                unsigned v;
                do {
                    asm volatile("ld.acquire.gpu.global.u32 %0, [%1];"
                                 : "=r"(v) : "l"((unsigned*)&g_bar) : "memory");
                } while (v < target);
            }
            __syncthreads();
        }
    }
}

// ---------------- final BN -> tanh -> Dense(H,10), fp16 h --------------------
__global__ void logits_kernel(const __half* __restrict__ hseq,
                              const float* __restrict__ g2, const float* __restrict__ b2,
                              const float* __restrict__ m2, const float* __restrict__ v2,
                              const float* __restrict__ Wout, float* __restrict__ out)
{
    int row = blockIdx.x;            // = t*BB + b
    int t = row / BB, b = row % BB;
    int tid = threadIdx.x;

    float a[CC];
#pragma unroll
    for (int c2 = 0; c2 < CC; c2++) a[c2] = 0.0f;

    const __half2* hp = (const __half2*)(hseq + (size_t)row*HH) + tid*2;
    __half2 h01 = hp[0], h23 = hp[1];
    float h4[4] = {__low2float(h01), __high2float(h01),
                   __low2float(h23), __high2float(h23)};

    float4 gv = *(const float4*)(g2 + tid*4);
    float4 bv = *(const float4*)(b2 + tid*4);
    float4 mv = *(const float4*)(m2 + tid*4);
    float4 vv = *(const float4*)(v2 + tid*4);
    float G4[4] = {gv.x, gv.y, gv.z, gv.w};
    float B4[4] = {bv.x, bv.y, bv.z, bv.w};
    float M4[4] = {mv.x, mv.y, mv.z, mv.w};
    float V4[4] = {vv.x, vv.y, vv.z, vv.w};

#pragma unroll
    for (int s = 0; s < 4; s++) {
        int k = tid*4 + s;
        float y = ftanh((h4[s] - M4[s]) * rsqrtf(V4[s] + BN_EPS) * G4[s] + B4[s]);
        const float* wr = Wout + (size_t)k*CC;
#pragma unroll
        for (int c2 = 0; c2 < CC; c2++)
            a[c2] = fmaf(y, wr[c2], a[c2]);
    }

#pragma unroll
    for (int off = 16; off > 0; off >>= 1)
#pragma unroll
        for (int c2 = 0; c2 < CC; c2++)
            a[c2] += __shfl_down_sync(0xffffffffu, a[c2], off);

    __shared__ float sacc[CC];
    if (tid < CC) sacc[tid] = 0.0f;
    __syncthreads();
    if ((tid & 31) == 0)
#pragma unroll
        for (int c2 = 0; c2 < CC; c2++) atomicAdd(&sacc[c2], a[c2]);
    __syncthreads();
    if (tid < CC)
        out[((size_t)b*TT + t)*CC + tid] = sacc[tid];
}

// ---------------- launcher ----------------------------------------------------
extern "C" void kernel_launch(void* const* d_in, const int* in_sizes, int n_in,
                              void* d_out, int out_size)
{
    const float* x      = (const float*)d_in[0];
    const float* W_fe   = (const float*)d_in[1];
    const float* b_fe   = (const float*)d_in[2];
    const float* gamma1 = (const float*)d_in[3];
    const float* beta1  = (const float*)d_in[4];
    const float* mean1  = (const float*)d_in[5];
    const float* var1   = (const float*)d_in[6];
    const float* Wg     = (const float*)d_in[7];
    const float* Wr     = (const float*)d_in[8];
    const float* bias   = (const float*)d_in[9];
    const float* pi     = (const float*)d_in[10];
    const float* pf     = (const float*)d_in[11];
    const float* po     = (const float*)d_in[12];
    const float* gamma2 = (const float*)d_in[13];
    const float* beta2  = (const float*)d_in[14];
    const float* mean2  = (const float*)d_in[15];
    const float* var2   = (const float*)d_in[16];
    const float* W_out  = (const float*)d_in[17];
    float* out = (float*)d_out;

    __half *xh, *wfe, *feat, *wg, *wrp, *hseq, *zx;
    float *biasP;
    cudaGetSymbolAddress((void**)&xh,    g_xh);
    cudaGetSymbolAddress((void**)&wfe,   g_wfe);
    cudaGetSymbolAddress((void**)&feat,  g_feat);
    cudaGetSymbolAddress((void**)&zx,    g_zx);
    cudaGetSymbolAddress((void**)&hseq,  g_hseq);
    cudaGetSymbolAddress((void**)&wg,    g_wg);
    cudaGetSymbolAddress((void**)&wrp,   g_wrp);
    cudaGetSymbolAddress((void**)&biasP, g_biasP);

    constexpr int G_SMEM = (2*256*72 + 2*64*136) * 2;   // 108544 B
    cudaFuncSetAttribute((const void*)gemm_f16<1>,
                         cudaFuncAttributeMaxDynamicSharedMemorySize, G_SMEM);
    cudaFuncSetAttribute((const void*)gemm_f16<2>,
                         cudaFuncAttributeMaxDynamicSharedMemorySize, G_SMEM);
    cudaFuncSetAttribute(lstm_persistent,
                         cudaFuncAttributeMaxDynamicSharedMemorySize, PSMEM_BYTES);

    init_kernel<<<1, 32>>>();

    // preprocess: pad/convert x; convert W_fe; permute Wg, Wr, bias
    {
        int n = M1 * FFP;
        pad_f16_kernel<<<(n + 255)/256, 256>>>(x, xh, M1, FF);

        int n2 = FF * HH / 2;
        f32_to_f16_kernel<<<(n2 + 255)/256, 256>>>((const float2*)W_fe, (__half2*)wfe, n2);
        cudaMemsetAsync(wfe + (size_t)FF * HH, 0, (size_t)(FFP - FF) * HH * sizeof(__half));

        int n3 = HH * 4 * HH;
        permute_w_kernel<<<(n3 + 255)/256, 256>>>(Wg, wg);
        permute_w_kernel<<<(n3 + 255)/256, 256>>>(Wr, wrp);
        permute_bias_kernel<<<(4*HH + 255)/256, 256>>>(bias, biasP);
    }

    // 1) feat (fp16, T-MAJOR) = tanh(BN(tanh(x @ W_fe + b_fe)))
    {
        dim3 grid(HH/128, M1/256);
        gemm_f16<1><<<grid, 512, G_SMEM>>>(xh, wfe, feat, M1, HH, FFP,
                                           b_fe, gamma1, beta1, mean1, var1);
    }
    // 2) Zx (fp16) = feat @ WgP + biasP   (cols j*4+g)
    {
        dim3 grid(4*HH/128, M1/256);
        gemm_f16<2><<<grid, 512, G_SMEM>>>(feat, wg, zx, M1, 4*HH, HH,
                                           biasP, nullptr, nullptr, nullptr, nullptr);
    }
    // 3) recurrence (fp16, B smem-resident, interleaved layout)
    lstm_persistent<<<128, 512, PSMEM_BYTES>>>(wrp, zx, hseq, pi, pf, po);
    // 4) logits
    logits_kernel<<<M1, 256>>>(hseq, gamma2, beta2, mean2, var2, W_out, out);
}